// round 7
// baseline (speedup 1.0000x reference)
#include <cuda_runtime.h>
#include <math.h>
#include <stdint.h>

#define NB 2
#define NS 1024
#define NT (NB*NS)      // 2048 tokens
#define ND 2048
#define NF 8192
#define NE 4

// ---------------- persistent scratch (device globals) ----------------------
__device__ float g_gatew[NE*NT];
__device__ int   g_counts[NE];
__device__ int   g_lists[NE*NT];
__device__ float g_H [(size_t)NE*NT*NF];   // H = silu(G)*U, tf32-rounded; rows >= Me stay 0
__device__ float g_Xr[(size_t)NT*ND];      // x, tf32-rounded

// ---------------- helpers ---------------------------------------------------
__device__ __forceinline__ uint32_t smem_u32(const void* p) {
    uint32_t a;
    asm("{ .reg .u64 t; cvta.to.shared.u64 t, %1; cvt.u32.u64 %0, t; }" : "=r"(a) : "l"(p));
    return a;
}
__device__ __forceinline__ unsigned f2tf(float f) {
    unsigned u; asm("cvt.rna.tf32.f32 %0, %1;" : "=r"(u) : "f"(f)); return u;
}
__device__ __forceinline__ float tf32r(float f) { return __uint_as_float(f2tf(f)); }

__device__ __forceinline__ void cpa16(uint32_t dst, const float* src) {
    asm volatile("cp.async.cg.shared.global [%0], [%1], 16;" :: "r"(dst), "l"(src));
}
__device__ __forceinline__ void cpa_commit() { asm volatile("cp.async.commit_group;"); }
__device__ __forceinline__ void cpa_wait1()  { asm volatile("cp.async.wait_group 1;"); }
__device__ __forceinline__ void cpa_wait0()  { asm volatile("cp.async.wait_group 0;"); }

__device__ __forceinline__ void mma8(float c[4], const unsigned a[4], const unsigned b[2]) {
    asm volatile(
        "mma.sync.aligned.m16n8k8.row.col.f32.tf32.tf32.f32 "
        "{%0,%1,%2,%3}, {%4,%5,%6,%7}, {%8,%9}, {%0,%1,%2,%3};"
        : "+f"(c[0]), "+f"(c[1]), "+f"(c[2]), "+f"(c[3])
        : "r"(a[0]), "r"(a[1]), "r"(a[2]), "r"(a[3]), "r"(b[0]), "r"(b[1]));
}
// ldmatrix x4 for tf32 A fragments: matrices 0..3 = (rows+0,k), (rows+8,k), (rows+0,k+4), (rows+8,k+4)
__device__ __forceinline__ void ldmA(unsigned r[4], uint32_t addr) {
    asm volatile("ldmatrix.sync.aligned.m8n8.x4.shared.b16 {%0,%1,%2,%3}, [%4];"
        : "=r"(r[0]), "=r"(r[1]), "=r"(r[2]), "=r"(r[3]) : "r"(addr));
}

// ---------------- trivial kernels -------------------------------------------
__global__ void zero_kernel(float* __restrict__ out) {
    size_t n = (size_t)NT * ND;
    for (size_t i = blockIdx.x * (size_t)blockDim.x + threadIdx.x; i < n;
         i += (size_t)gridDim.x * blockDim.x) out[i] = 0.f;
    if (blockIdx.x == 0 && threadIdx.x < NE) g_counts[threadIdx.x] = 0;
}

__global__ void round_copy(const float* __restrict__ src, float* __restrict__ dst, size_t n4) {
    for (size_t i = blockIdx.x * (size_t)blockDim.x + threadIdx.x; i < n4;
         i += (size_t)gridDim.x * blockDim.x) {
        float4 v = ((const float4*)src)[i];
        ((float4*)dst)[i] = make_float4(tf32r(v.x), tf32r(v.y), tf32r(v.z), tf32r(v.w));
    }
}

__global__ void router_kernel(const float* __restrict__ x, const float* __restrict__ Wr) {
    int t = blockIdx.x;
    const float* xr = x + (size_t)t * ND;
    float acc[NE] = {0.f, 0.f, 0.f, 0.f};
    for (int d = threadIdx.x; d < ND; d += blockDim.x) {
        float xv = xr[d];
        float4 w = *(const float4*)(Wr + d * NE);
        acc[0] += xv * w.x; acc[1] += xv * w.y; acc[2] += xv * w.z; acc[3] += xv * w.w;
    }
    __shared__ float sred[NE][8];
    int lane = threadIdx.x & 31, wid = threadIdx.x >> 5;
    #pragma unroll
    for (int e = 0; e < NE; e++) {
        float s = acc[e];
        #pragma unroll
        for (int off = 16; off > 0; off >>= 1) s += __shfl_down_sync(0xffffffffu, s, off);
        if (lane == 0) sred[e][wid] = s;
    }
    __syncthreads();
    if (threadIdx.x == 0) {
        float l[NE];
        #pragma unroll
        for (int e = 0; e < NE; e++) {
            float s = 0.f;
            #pragma unroll
            for (int w = 0; w < 8; w++) s += sred[e][w];
            l[e] = s;
        }
        float mx = fmaxf(fmaxf(l[0], l[1]), fmaxf(l[2], l[3]));
        float ex[NE], ssum = 0.f;
        #pragma unroll
        for (int e = 0; e < NE; e++) { ex[e] = expf(l[e] - mx); ssum += ex[e]; }
        float p[NE];
        #pragma unroll
        for (int e = 0; e < NE; e++) p[e] = ex[e] / ssum;
        int i1 = 0;
        #pragma unroll
        for (int e = 1; e < NE; e++) if (p[e] > p[i1]) i1 = e;
        int i2 = -1;
        #pragma unroll
        for (int e = 0; e < NE; e++)
            if (e != i1 && (i2 < 0 || p[e] > p[i2])) i2 = e;
        #pragma unroll
        for (int e = 0; e < NE; e++)
            g_gatew[e * NT + t] = (e == i1 || e == i2) ? p[e] : 0.f;
    }
}

__global__ void compact_kernel() {
    for (int t = threadIdx.x; t < NT; t += blockDim.x) {
        #pragma unroll
        for (int e = 0; e < NE; e++) {
            if (g_gatew[e * NT + t] > 0.f) {
                int p = atomicAdd(&g_counts[e], 1);
                g_lists[e * NT + p] = t;
            }
        }
    }
}

// ---------------------------------------------------------------------------
// GATE+UP fused GEMM. 512 threads, BM=128, BN_F=128 (G||U -> 256 N), BK=16.
// 16 warps 4(wm) x 4(wn): wn<2 -> G warps, wn>=2 -> U warps; warp tile 32x64.
// A: [128 rows][16 k] stride 20 words (ldmatrix, conflict-free)
// Bg/Bu: [16 k][128 n] stride 136 words (conflict-free fragment LDS)
// Epilogue: U warps stash accs in smem; G warps apply silu(G)*U -> g_H.
// ---------------------------------------------------------------------------
#define GU_AF 2560                       // 128*20 floats
#define GU_BF 2176                       // 16*136 floats
#define GU_STAGEF (GU_AF + 2*GU_BF)      // 6912 floats = 27648 B
#define GU_SMEM (3 * GU_STAGEF * 4)      // 82944 B   (U_s 128*132*4=67584 aliases this)

__global__ __launch_bounds__(512, 1) void gateup_tc(const float* __restrict__ X,
                                                    const float* __restrict__ Wg,
                                                    const float* __restrict__ Wu) {
    const int e  = blockIdx.z;
    const int Me = g_counts[e];
    const int m0 = blockIdx.x * 128;
    if (m0 >= Me) return;
    const int n0 = blockIdx.y * 128;

    extern __shared__ float smem[];
    const uint32_t sb0 = smem_u32(smem);

    const int tid  = threadIdx.x;
    const int warp = tid >> 5;
    const int lane = tid & 31;
    const int g4   = lane >> 2;
    const int t4   = lane & 3;
    const int wm   = warp >> 2;          // 0..3
    const int wn   = warp & 3;           // 0..3
    const int mat  = wn >> 1;            // 0=G, 1=U
    const int hn   = wn & 1;             // n-half within matrix

    // ---- staging maps ----
    // A: one float4 per thread: row = tid>>2 (0..127), q = tid&3 (k-chunk)
    const int arow = tid >> 2, aq = tid & 3;
    int mrow = m0 + arow; if (mrow >= Me) mrow = Me - 1;
    const float* asrc = X + (size_t)g_lists[e * NT + mrow] * ND + aq * 4;
    const uint32_t adst = sb0 + (arow * 20 + aq * 4) * 4;
    // B: two float4 per thread over G+U (1024 fl4): linear = j*512 + tid
    //    matl = linear>>9, rem = linear&511: row = rem>>5, c4 = rem&31
    const float* wsrc[2] = { Wg + (size_t)e * ND * NF + n0,
                             Wu + (size_t)e * ND * NF + n0 };

    float acc[2][8][4];
    #pragma unroll
    for (int i = 0; i < 2; i++)
        #pragma unroll
        for (int j = 0; j < 8; j++)
            #pragma unroll
            for (int k = 0; k < 4; k++) acc[i][j][k] = 0.f;

    const int KT = ND / 16;    // 128
    auto issue = [&](int it) {
        const uint32_t so = (uint32_t)(it % 3) * (GU_STAGEF * 4);
        const size_t ka = (size_t)it * 16;
        cpa16(adst + so, asrc + ka);
        #pragma unroll
        for (int j = 0; j < 2; j++) {
            const int linear = j * 512 + tid;
            const int matl = linear >> 9, rem = linear & 511;
            const int row = rem >> 5, c4 = rem & 31;
            cpa16(sb0 + so + (GU_AF + matl * GU_BF + row * 136 + c4 * 4) * 4,
                  wsrc[matl] + (ka + row) * NF + c4 * 4);
        }
    };

    issue(0); cpa_commit();
    issue(1); cpa_commit();

    // ldmatrix lane offset (bytes) within A stage: rows (wm*32+mi*16 + lane&15), k + (lane>=16)*4
    const uint32_t aldm = ((wm * 32 + (lane & 15)) * 20 + ((lane >> 4) << 2)) * 4;
    const int bbase_w = GU_AF + mat * GU_BF + hn * 64;   // word offset of this warp's B cols

    for (int it = 0; it < KT; ++it) {
        cpa_wait1();
        __syncthreads();
        if (it + 2 < KT) issue(it + 2);
        cpa_commit();

        const uint32_t sA = sb0 + (uint32_t)(it % 3) * (GU_STAGEF * 4);
        const float* Bs = smem + (it % 3) * GU_STAGEF + bbase_w;

        #pragma unroll
        for (int ks = 0; ks < 16; ks += 8) {
            unsigned a[2][4];
            #pragma unroll
            for (int mi = 0; mi < 2; mi++)
                ldmA(a[mi], sA + aldm + (mi * 16 * 20 + ks) * 4);
            #pragma unroll
            for (int ni = 0; ni < 8; ni++) {
                const int nb = ni * 8 + g4;
                unsigned b[2] = { f2tf(Bs[(ks + t4) * 136 + nb]),
                                  f2tf(Bs[(ks + t4 + 4) * 136 + nb]) };
                #pragma unroll
                for (int mi = 0; mi < 2; mi++)
                    mma8(acc[mi][ni], a[mi], b);
            }
        }
    }

    // ---- epilogue: exchange U via smem, G warps write H = tf32(silu(G)*U) ----
    cpa_wait0();
    __syncthreads();                      // stage buffers free; reuse as U_s[128][132]
    float* Us = smem;
    if (mat == 1) {                       // U warps stash
        #pragma unroll
        for (int mi = 0; mi < 2; mi++)
            #pragma unroll
            for (int half = 0; half < 2; half++) {
                const int ml = wm * 32 + mi * 16 + g4 + half * 8;
                #pragma unroll
                for (int ni = 0; ni < 8; ni++) {
                    const int col = hn * 64 + ni * 8 + 2 * t4;
                    *(float2*)(Us + ml * 132 + col) =
                        make_float2(acc[mi][ni][half * 2], acc[mi][ni][half * 2 + 1]);
                }
            }
    }
    __syncthreads();
    if (mat == 0) {                       // G warps combine + write
        #pragma unroll
        for (int mi = 0; mi < 2; mi++)
            #pragma unroll
            for (int half = 0; half < 2; half++) {
                const int ml = wm * 32 + mi * 16 + g4 + half * 8;
                const int m  = m0 + ml;
                if (m >= Me) continue;
                float* Hrow = g_H + ((size_t)e * NT + m) * NF + n0 + hn * 64;
                #pragma unroll
                for (int ni = 0; ni < 8; ni++) {
                    const int col = hn * 64 + ni * 8 + 2 * t4;
                    float2 u = *(const float2*)(Us + ml * 132 + col);
                    float gv0 = acc[mi][ni][half * 2], gv1 = acc[mi][ni][half * 2 + 1];
                    float h0 = tf32r(gv0 / (1.f + expf(-gv0)) * u.x);
                    float h1 = tf32r(gv1 / (1.f + expf(-gv1)) * u.y);
                    *(float2*)(Hrow + ni * 8 + 2 * t4) = make_float2(h0, h1);
                }
            }
    }
}

// ---------------------------------------------------------------------------
// DOWN GEMM + combine. 512 threads, BM=256, BN=128, BK=16.
// 16 warps 8(wm) x 2(wn), warp tile 32x64.
// A: [256 rows][16 k] stride 20 (ldmatrix); B: [16 k][128 n] stride 136.
// ---------------------------------------------------------------------------
#define DN_AF 5120                       // 256*20
#define DN_BF 2176                       // 16*136
#define DN_STAGEF (DN_AF + DN_BF)        // 7296 floats = 29184 B
#define DN_SMEM (3 * DN_STAGEF * 4)      // 87552 B

__global__ __launch_bounds__(512, 1) void down_tc(const float* __restrict__ Wd,
                                                  float* __restrict__ OUT) {
    const int e  = blockIdx.z;
    const int Me = g_counts[e];
    const int m0 = blockIdx.x * 256;
    if (m0 >= Me) return;
    const int n0 = blockIdx.y * 128;

    extern __shared__ float smem[];
    const uint32_t sb0 = smem_u32(smem);

    const int tid  = threadIdx.x;
    const int warp = tid >> 5;
    const int lane = tid & 31;
    const int g4   = lane >> 2;
    const int t4   = lane & 3;
    const int wm   = warp >> 1;          // 0..7
    const int wn   = warp & 1;           // 0..1

    // A: two float4 per thread (1024 fl4): linear = j*512 + tid: row = lin>>2, q = lin&3
    const float* abase = g_H + ((size_t)e * NT + m0) * NF;   // rows >= Me read zeros
    // B: one float4 per thread: row = tid>>5, c4 = tid&31
    const int brr = tid >> 5, bc4 = tid & 31;
    const float* bsrc = Wd + (size_t)e * NF * ND + n0 + bc4 * 4;
    const uint32_t bdst = sb0 + (DN_AF + brr * 136 + bc4 * 4) * 4;

    float acc[2][8][4];
    #pragma unroll
    for (int i = 0; i < 2; i++)
        #pragma unroll
        for (int j = 0; j < 8; j++)
            #pragma unroll
            for (int k = 0; k < 4; k++) acc[i][j][k] = 0.f;

    const int KT = NF / 16;   // 512
    auto issue = [&](int it) {
        const uint32_t so = (uint32_t)(it % 3) * (DN_STAGEF * 4);
        const size_t ka = (size_t)it * 16;
        #pragma unroll
        for (int j = 0; j < 2; j++) {
            const int linear = j * 512 + tid;
            const int row = linear >> 2, q = linear & 3;
            cpa16(sb0 + so + (row * 20 + q * 4) * 4, abase + (size_t)row * NF + ka + q * 4);
        }
        cpa16(bdst + so, bsrc + (ka + brr) * ND);
    };

    issue(0); cpa_commit();
    issue(1); cpa_commit();

    const uint32_t aldm = ((wm * 32 + (lane & 15)) * 20 + ((lane >> 4) << 2)) * 4;

    for (int it = 0; it < KT; ++it) {
        cpa_wait1();
        __syncthreads();
        if (it + 2 < KT) issue(it + 2);
        cpa_commit();

        const uint32_t sA = sb0 + (uint32_t)(it % 3) * (DN_STAGEF * 4);
        const float* Bs = smem + (it % 3) * DN_STAGEF + DN_AF + wn * 64;

        #pragma unroll
        for (int ks = 0; ks < 16; ks += 8) {
            unsigned a[2][4];
            #pragma unroll
            for (int mi = 0; mi < 2; mi++)
                ldmA(a[mi], sA + aldm + (mi * 16 * 20 + ks) * 4);
            #pragma unroll
            for (int ni = 0; ni < 8; ni++) {
                const int nb = ni * 8 + g4;
                unsigned b[2] = { f2tf(Bs[(ks + t4) * 136 + nb]),
                                  f2tf(Bs[(ks + t4 + 4) * 136 + nb]) };
                #pragma unroll
                for (int mi = 0; mi < 2; mi++)
                    mma8(acc[mi][ni], a[mi], b);
            }
        }
    }

    #pragma unroll
    for (int mi = 0; mi < 2; mi++) {
        #pragma unroll
        for (int half = 0; half < 2; half++) {
            const int m = m0 + wm * 32 + mi * 16 + g4 + half * 8;
            if (m >= Me) continue;
            const int tok = g_lists[e * NT + m];
            const float w = g_gatew[e * NT + tok];
            float* dst = OUT + (size_t)tok * ND + n0 + wn * 64;
            #pragma unroll
            for (int ni = 0; ni < 8; ni++) {
                atomicAdd(dst + ni * 8 + 2 * t4,     w * acc[mi][ni][half * 2]);
                atomicAdd(dst + ni * 8 + 2 * t4 + 1, w * acc[mi][ni][half * 2 + 1]);
            }
        }
    }
}

// ---------------------------------------------------------------------------
extern "C" void kernel_launch(void* const* d_in, const int* in_sizes, int n_in,
                              void* d_out, int out_size) {
    const float* x  = (const float*)d_in[0];
    const float* Wr = (const float*)d_in[1];
    const float* Wg = (const float*)d_in[2];
    const float* Wu = (const float*)d_in[3];
    const float* Wd = (const float*)d_in[4];
    float* out = (float*)d_out;

    cudaFuncSetAttribute(gateup_tc, cudaFuncAttributeMaxDynamicSharedMemorySize, GU_SMEM);
    cudaFuncSetAttribute(down_tc,   cudaFuncAttributeMaxDynamicSharedMemorySize, DN_SMEM);

    float* xr;  cudaGetSymbolAddress((void**)&xr, g_Xr);

    zero_kernel<<<2048, 256>>>(out);
    router_kernel<<<NT, 256>>>(x, Wr);
    compact_kernel<<<1, 256>>>();
    round_copy<<<2048, 256>>>(x, xr, (size_t)NT * ND / 4);

    gateup_tc<<<dim3(NT/128, NF/128, NE), 512, GU_SMEM>>>(xr, Wg, Wu);
    down_tc  <<<dim3(NT/256, ND/128, NE), 512, DN_SMEM>>>(Wd, out);
}

// round 8
// speedup vs baseline: 1.6282x; 1.6282x over previous
#include <cuda_runtime.h>
#include <math.h>
#include <stdint.h>

#define NB 2
#define NS 1024
#define NT (NB*NS)      // 2048 tokens
#define ND 2048
#define NF 8192
#define NE 4

// ---------------- persistent scratch (device globals) ----------------------
__device__ float g_gatew[NE*NT];
__device__ int   g_counts[NE];
__device__ int   g_lists[NE*NT];
__device__ float g_H [(size_t)NE*NT*NF];   // H = silu(G)*U, tf32-rounded; rows >= Me stay 0
__device__ float g_Xr[(size_t)NT*ND];      // x, tf32-rounded

// ---------------- helpers ---------------------------------------------------
__device__ __forceinline__ uint32_t smem_u32(const void* p) {
    uint32_t a;
    asm("{ .reg .u64 t; cvta.to.shared.u64 t, %1; cvt.u32.u64 %0, t; }" : "=r"(a) : "l"(p));
    return a;
}
__device__ __forceinline__ unsigned f2tf(float f) {
    unsigned u; asm("cvt.rna.tf32.f32 %0, %1;" : "=r"(u) : "f"(f)); return u;
}
__device__ __forceinline__ float tf32r(float f) { return __uint_as_float(f2tf(f)); }

__device__ __forceinline__ void cpa16(uint32_t dst, const float* src) {
    asm volatile("cp.async.cg.shared.global [%0], [%1], 16;" :: "r"(dst), "l"(src));
}
__device__ __forceinline__ void cpa_commit() { asm volatile("cp.async.commit_group;"); }
__device__ __forceinline__ void cpa_wait2()  { asm volatile("cp.async.wait_group 2;"); }

__device__ __forceinline__ void mma8(float c[4], const unsigned a[4], const unsigned b[2]) {
    asm volatile(
        "mma.sync.aligned.m16n8k8.row.col.f32.tf32.tf32.f32 "
        "{%0,%1,%2,%3}, {%4,%5,%6,%7}, {%8,%9}, {%0,%1,%2,%3};"
        : "+f"(c[0]), "+f"(c[1]), "+f"(c[2]), "+f"(c[3])
        : "r"(a[0]), "r"(a[1]), "r"(a[2]), "r"(a[3]), "r"(b[0]), "r"(b[1]));
}
// ldmatrix x4 on the stride-20 A tile (lane mapping validated in R7: bit-identical results)
__device__ __forceinline__ void ldmA(unsigned r[4], uint32_t addr) {
    asm volatile("ldmatrix.sync.aligned.m8n8.x4.shared.b16 {%0,%1,%2,%3}, [%4];"
        : "=r"(r[0]), "=r"(r[1]), "=r"(r[2]), "=r"(r[3]) : "r"(addr));
}

// ---------------- trivial kernels -------------------------------------------
__global__ void zero_kernel(float* __restrict__ out) {
    size_t n = (size_t)NT * ND;
    for (size_t i = blockIdx.x * (size_t)blockDim.x + threadIdx.x; i < n;
         i += (size_t)gridDim.x * blockDim.x) out[i] = 0.f;
    if (blockIdx.x == 0 && threadIdx.x < NE) g_counts[threadIdx.x] = 0;
}

__global__ void round_copy(const float* __restrict__ src, float* __restrict__ dst, size_t n4) {
    for (size_t i = blockIdx.x * (size_t)blockDim.x + threadIdx.x; i < n4;
         i += (size_t)gridDim.x * blockDim.x) {
        float4 v = ((const float4*)src)[i];
        ((float4*)dst)[i] = make_float4(tf32r(v.x), tf32r(v.y), tf32r(v.z), tf32r(v.w));
    }
}

__global__ void router_kernel(const float* __restrict__ x, const float* __restrict__ Wr) {
    int t = blockIdx.x;
    const float* xr = x + (size_t)t * ND;
    float acc[NE] = {0.f, 0.f, 0.f, 0.f};
    for (int d = threadIdx.x; d < ND; d += blockDim.x) {
        float xv = xr[d];
        float4 w = *(const float4*)(Wr + d * NE);
        acc[0] += xv * w.x; acc[1] += xv * w.y; acc[2] += xv * w.z; acc[3] += xv * w.w;
    }
    __shared__ float sred[NE][8];
    int lane = threadIdx.x & 31, wid = threadIdx.x >> 5;
    #pragma unroll
    for (int e = 0; e < NE; e++) {
        float s = acc[e];
        #pragma unroll
        for (int off = 16; off > 0; off >>= 1) s += __shfl_down_sync(0xffffffffu, s, off);
        if (lane == 0) sred[e][wid] = s;
    }
    __syncthreads();
    if (threadIdx.x == 0) {
        float l[NE];
        #pragma unroll
        for (int e = 0; e < NE; e++) {
            float s = 0.f;
            #pragma unroll
            for (int w = 0; w < 8; w++) s += sred[e][w];
            l[e] = s;
        }
        float mx = fmaxf(fmaxf(l[0], l[1]), fmaxf(l[2], l[3]));
        float ex[NE], ssum = 0.f;
        #pragma unroll
        for (int e = 0; e < NE; e++) { ex[e] = expf(l[e] - mx); ssum += ex[e]; }
        float p[NE];
        #pragma unroll
        for (int e = 0; e < NE; e++) p[e] = ex[e] / ssum;
        int i1 = 0;
        #pragma unroll
        for (int e = 1; e < NE; e++) if (p[e] > p[i1]) i1 = e;
        int i2 = -1;
        #pragma unroll
        for (int e = 0; e < NE; e++)
            if (e != i1 && (i2 < 0 || p[e] > p[i2])) i2 = e;
        #pragma unroll
        for (int e = 0; e < NE; e++)
            g_gatew[e * NT + t] = (e == i1 || e == i2) ? p[e] : 0.f;
    }
}

__global__ void compact_kernel() {
    for (int t = threadIdx.x; t < NT; t += blockDim.x) {
        #pragma unroll
        for (int e = 0; e < NE; e++) {
            if (g_gatew[e * NT + t] > 0.f) {
                int p = atomicAdd(&g_counts[e], 1);
                g_lists[e * NT + p] = t;
            }
        }
    }
}

// ---------------------------------------------------------------------------
// GATE+UP fused GEMM (tf32 mma.sync, cp.async 4-stage pipeline, 256 thr, 2 CTA/SM)
// Block tile M=128, N=64 (per matrix), K=16.  8 warps 4x2 -> 32x32 warptile each.
// A tile:  [128 rows][16 k] k-contiguous, row stride 20 words (ldmatrix, conflict-free)
// B tiles: [16 k][64 n]  n-contiguous, row stride 72 words (conflict-free)
// A pre-rounded tf32 (g_Xr); B RAW fp32, rounded RNA at fragment load.
// ---------------------------------------------------------------------------
#define GU_AF 2560          // 128*20 floats
#define GU_BF 1152          // 16*72 floats
#define GU_STAGEF (GU_AF + 2*GU_BF)           // 4864 floats = 19456 B
#define GU_SMEM (4 * GU_STAGEF * 4)           // 77824 B

__global__ __launch_bounds__(256, 2) void gateup_tc(const float* __restrict__ X,
                                                    const float* __restrict__ Wg,
                                                    const float* __restrict__ Wu) {
    const int e  = blockIdx.z;
    const int Me = g_counts[e];
    const int m0 = blockIdx.x * 128;
    if (m0 >= Me) return;
    const int n0 = blockIdx.y * 64;

    extern __shared__ float smem[];
    const uint32_t sb0 = smem_u32(smem);

    const int tid  = threadIdx.x;
    const int warp = tid >> 5;
    const int lane = tid & 31;
    const int g4   = lane >> 2;
    const int t4   = lane & 3;
    const int wm   = warp >> 1;        // 0..3
    const int wn   = warp & 1;         // 0..1

    const int ar = tid >> 1;
    const int ah = (tid & 1) * 8;
    int mrow = m0 + ar; if (mrow >= Me) mrow = Me - 1;
    const float* asrc = X + (size_t)g_lists[e * NT + mrow] * ND + ah;
    const uint32_t adst = sb0 + (ar * 20 + ah) * 4;
    const int brr = tid >> 4;
    const int bcc = tid & 15;
    const float* bgsrc = Wg + (size_t)e * ND * NF + (size_t)brr * NF + n0 + bcc * 4;
    const float* busrc = Wu + (size_t)e * ND * NF + (size_t)brr * NF + n0 + bcc * 4;
    const uint32_t bgdst = sb0 + (GU_AF + brr * 72 + bcc * 4) * 4;
    const uint32_t budst = sb0 + (GU_AF + GU_BF + brr * 72 + bcc * 4) * 4;

    float accG[2][4][4], accU[2][4][4];
    #pragma unroll
    for (int i = 0; i < 2; i++)
        #pragma unroll
        for (int j = 0; j < 4; j++)
            #pragma unroll
            for (int k = 0; k < 4; k++) { accG[i][j][k] = 0.f; accU[i][j][k] = 0.f; }

    const int KT = ND / 16;    // 128
    auto issue = [&](int it) {
        const uint32_t so = (uint32_t)(it & 3) * (GU_STAGEF * 4);
        const size_t ka = (size_t)it * 16;
        cpa16(adst + so,      asrc + ka);
        cpa16(adst + so + 16, asrc + ka + 4);
        cpa16(bgdst + so, bgsrc + ka * NF);
        cpa16(budst + so, busrc + ka * NF);
    };

    issue(0); cpa_commit();
    issue(1); cpa_commit();
    issue(2); cpa_commit();

    // ldmatrix lane offset (bytes): rows (wm*32 + (lane&15)), k-offset (lane>=16)*4
    const uint32_t aldm = ((wm * 32 + (lane & 15)) * 20 + ((lane >> 4) << 2)) * 4;

    for (int it = 0; it < KT; ++it) {
        cpa_wait2();               // groups {it..it+2} pending -> group it complete
        __syncthreads();           // all warps past stage it-1 before overwrite
        if (it + 3 < KT) issue(it + 3);
        cpa_commit();

        const uint32_t sA = sb0 + (uint32_t)(it & 3) * (GU_STAGEF * 4);
        const float* Bg = smem + (it & 3) * GU_STAGEF + GU_AF;
        const float* Bu = Bg + GU_BF;

        #pragma unroll
        for (int ks = 0; ks < 16; ks += 8) {
            unsigned a[2][4];
            #pragma unroll
            for (int mi = 0; mi < 2; mi++)
                ldmA(a[mi], sA + aldm + (mi * 16 * 20 + ks) * 4);
            #pragma unroll
            for (int ni = 0; ni < 4; ni++) {
                const int nb = wn * 32 + ni * 8 + g4;
                unsigned bg[2] = { f2tf(Bg[(ks + t4) * 72 + nb]),
                                   f2tf(Bg[(ks + t4 + 4) * 72 + nb]) };
                unsigned bu[2] = { f2tf(Bu[(ks + t4) * 72 + nb]),
                                   f2tf(Bu[(ks + t4 + 4) * 72 + nb]) };
                #pragma unroll
                for (int mi = 0; mi < 2; mi++) {
                    mma8(accG[mi][ni], a[mi], bg);
                    mma8(accU[mi][ni], a[mi], bu);
                }
            }
        }
    }

    // epilogue: H = tf32( silu(G)*U )
    #pragma unroll
    for (int mi = 0; mi < 2; mi++) {
        #pragma unroll
        for (int half = 0; half < 2; half++) {
            const int m = m0 + wm * 32 + mi * 16 + g4 + half * 8;
            if (m >= Me) continue;
            float* Hrow = g_H + ((size_t)e * NT + m) * NF + n0 + wn * 32;
            #pragma unroll
            for (int ni = 0; ni < 4; ni++) {
                float gv0 = accG[mi][ni][half * 2],     uv0 = accU[mi][ni][half * 2];
                float gv1 = accG[mi][ni][half * 2 + 1], uv1 = accU[mi][ni][half * 2 + 1];
                float h0 = tf32r(gv0 / (1.f + expf(-gv0)) * uv0);
                float h1 = tf32r(gv1 / (1.f + expf(-gv1)) * uv1);
                *(float2*)(Hrow + ni * 8 + 2 * t4) = make_float2(h0, h1);
            }
        }
    }
}

// ---------------------------------------------------------------------------
// DOWN GEMM + combine (tf32 mma.sync, cp.async 4-stage pipeline, 256 thr, 2 CTA/SM)
// Block tile 128x128x16. 8 warps 4x2 -> 32x64 warptile.
// A row stride 20 (ldmatrix); B row stride 136.
// ---------------------------------------------------------------------------
#define DN_AF 2560          // 128*20
#define DN_BF 2176          // 16*136
#define DN_STAGEF (DN_AF + DN_BF)             // 4736 floats = 18944 B
#define DN_SMEM (4 * DN_STAGEF * 4)           // 75776 B

__global__ __launch_bounds__(256, 2) void down_tc(const float* __restrict__ Wd,
                                                  float* __restrict__ OUT) {
    const int e  = blockIdx.z;
    const int Me = g_counts[e];
    const int m0 = blockIdx.x * 128;
    if (m0 >= Me) return;
    const int n0 = blockIdx.y * 128;

    extern __shared__ float smem[];
    const uint32_t sb0 = smem_u32(smem);

    const int tid  = threadIdx.x;
    const int warp = tid >> 5;
    const int lane = tid & 31;
    const int g4   = lane >> 2;
    const int t4   = lane & 3;
    const int wm   = warp >> 1;
    const int wn   = warp & 1;

    const int ar = tid >> 1;
    const int ah = (tid & 1) * 8;
    const float* asrc = g_H + ((size_t)e * NT + m0 + ar) * NF + ah;  // rows>=Me read zeros
    const uint32_t adst = sb0 + (ar * 20 + ah) * 4;

    const int br0 = tid >> 5, bc0 = tid & 31;
    const float* bsrc = Wd + (size_t)e * NF * ND + n0;
    const uint32_t bbase = sb0 + DN_AF * 4;

    float acc[2][8][4];
    #pragma unroll
    for (int i = 0; i < 2; i++)
        #pragma unroll
        for (int j = 0; j < 8; j++)
            #pragma unroll
            for (int k = 0; k < 4; k++) acc[i][j][k] = 0.f;

    const int KT = NF / 16;   // 512
    auto issue = [&](int it) {
        const uint32_t so = (uint32_t)(it & 3) * (DN_STAGEF * 4);
        const size_t ka = (size_t)it * 16;
        cpa16(adst + so,      asrc + ka);
        cpa16(adst + so + 16, asrc + ka + 4);
        #pragma unroll
        for (int j = 0; j < 2; j++) {
            const int row = br0 + j * 8;
            cpa16(bbase + so + (row * 136 + bc0 * 4) * 4, bsrc + (ka + row) * ND + bc0 * 4);
        }
    };

    issue(0); cpa_commit();
    issue(1); cpa_commit();
    issue(2); cpa_commit();

    const uint32_t aldm = ((wm * 32 + (lane & 15)) * 20 + ((lane >> 4) << 2)) * 4;

    for (int it = 0; it < KT; ++it) {
        cpa_wait2();
        __syncthreads();
        if (it + 3 < KT) issue(it + 3);
        cpa_commit();

        const uint32_t sA = sb0 + (uint32_t)(it & 3) * (DN_STAGEF * 4);
        const float* Bs = smem + (it & 3) * DN_STAGEF + DN_AF;

        #pragma unroll
        for (int ks = 0; ks < 16; ks += 8) {
            unsigned a[2][4];
            #pragma unroll
            for (int mi = 0; mi < 2; mi++)
                ldmA(a[mi], sA + aldm + (mi * 16 * 20 + ks) * 4);
            #pragma unroll
            for (int ni = 0; ni < 8; ni++) {
                const int nb = wn * 64 + ni * 8 + g4;
                unsigned b[2] = { f2tf(Bs[(ks + t4) * 136 + nb]),
                                  f2tf(Bs[(ks + t4 + 4) * 136 + nb]) };
                #pragma unroll
                for (int mi = 0; mi < 2; mi++)
                    mma8(acc[mi][ni], a[mi], b);
            }
        }
    }

    #pragma unroll
    for (int mi = 0; mi < 2; mi++) {
        #pragma unroll
        for (int half = 0; half < 2; half++) {
            const int m = m0 + wm * 32 + mi * 16 + g4 + half * 8;
            if (m >= Me) continue;
            const int tok = g_lists[e * NT + m];
            const float w = g_gatew[e * NT + tok];
            float* dst = OUT + (size_t)tok * ND + n0 + wn * 64;
            #pragma unroll
            for (int ni = 0; ni < 8; ni++) {
                atomicAdd(dst + ni * 8 + 2 * t4,     w * acc[mi][ni][half * 2]);
                atomicAdd(dst + ni * 8 + 2 * t4 + 1, w * acc[mi][ni][half * 2 + 1]);
            }
        }
    }
}

// ---------------------------------------------------------------------------
extern "C" void kernel_launch(void* const* d_in, const int* in_sizes, int n_in,
                              void* d_out, int out_size) {
    const float* x  = (const float*)d_in[0];
    const float* Wr = (const float*)d_in[1];
    const float* Wg = (const float*)d_in[2];
    const float* Wu = (const float*)d_in[3];
    const float* Wd = (const float*)d_in[4];
    float* out = (float*)d_out;

    cudaFuncSetAttribute(gateup_tc, cudaFuncAttributeMaxDynamicSharedMemorySize, GU_SMEM);
    cudaFuncSetAttribute(down_tc,   cudaFuncAttributeMaxDynamicSharedMemorySize, DN_SMEM);

    float* xr;  cudaGetSymbolAddress((void**)&xr, g_Xr);

    zero_kernel<<<2048, 256>>>(out);
    router_kernel<<<NT, 256>>>(x, Wr);
    compact_kernel<<<1, 256>>>();
    round_copy<<<2048, 256>>>(x, xr, (size_t)NT * ND / 4);

    gateup_tc<<<dim3(NT/128, NF/64, NE), 256, GU_SMEM>>>(xr, Wg, Wu);
    down_tc  <<<dim3(NT/128, ND/128, NE), 256, DN_SMEM>>>(Wd, out);
}